// round 8
// baseline (speedup 1.0000x reference)
#include <cuda_runtime.h>
#include <cuda_fp16.h>
#include <cstdint>

#define BB 4
#define TT 2048
#define CC 64
#define HH 6
#define DD 64
#define BH (BB*HH)
#define NEG_BIG (-1e30f)

// ---------------------------------------------------------------------------
// Scratch (__device__ globals; allocation-free rule). fp16 hi/lo splits.
// ---------------------------------------------------------------------------
__device__ __half g_xh [(size_t)BB*TT*CC];   // x split hi/lo
__device__ __half g_xl [(size_t)BB*TT*CC];
__device__ __half g_yh [(size_t)BB*TT*CC];   // y split hi/lo
__device__ __half g_yl [(size_t)BB*TT*CC];
__device__ __half g_wTh[(size_t)3*HH*CC*DD]; // W transposed [sel*H+h][d][c] hi/lo
__device__ __half g_wTl[(size_t)3*HH*CC*DD];

__device__ __half g_qh [(size_t)BH*TT*DD];   // q (pre-scaled by 0.125, hi only)
__device__ __half g_kh [(size_t)BH*TT*DD];
__device__ __half g_kl [(size_t)BH*TT*DD];
__device__ __half g_vth[(size_t)BH*DD*TT];   // v transposed: [bh][d][t]
__device__ __half g_vtl[(size_t)BH*DD*TT];
__device__ float  g_o  [(size_t)BH*TT*DD];

__device__ __forceinline__ uint32_t smem_u32(const void* p) {
    uint32_t a;
    asm("{ .reg .u64 t; cvta.to.shared.u64 t, %1; cvt.u32.u64 %0, t; }"
        : "=r"(a) : "l"(p));
    return a;
}

#define LDMATRIX_X4(r0, r1, r2, r3, addr) \
    asm volatile("ldmatrix.sync.aligned.m8n8.x4.shared.b16 {%0,%1,%2,%3}, [%4];" \
        : "=r"(r0), "=r"(r1), "=r"(r2), "=r"(r3) : "r"(addr))

#define MMA_F16(d0, d1, d2, d3, a0, a1, a2, a3, b0, b1) \
    asm volatile("mma.sync.aligned.m16n8k16.row.col.f32.f16.f16.f32 " \
        "{%0,%1,%2,%3}, {%4,%5,%6,%7}, {%8,%9}, {%0,%1,%2,%3};" \
        : "+f"(d0), "+f"(d1), "+f"(d2), "+f"(d3) \
        : "r"(a0), "r"(a1), "r"(a2), "r"(a3), "r"(b0), "r"(b1))

#define CP_ASYNC16(saddr, gaddr) \
    asm volatile("cp.async.cg.shared.global [%0], [%1], 16;" \
        :: "r"(saddr), "l"(gaddr) : "memory")
#define CP_COMMIT() asm volatile("cp.async.commit_group;" ::: "memory")
#define CP_WAIT0()  asm volatile("cp.async.wait_group 0;" ::: "memory")

__device__ __forceinline__ uint32_t pack_h2(__half a, __half b) {
    return (uint32_t)__half_as_ushort(a) | ((uint32_t)__half_as_ushort(b) << 16);
}
__device__ __forceinline__ void split_h(float v, __half& hi, __half& lo) {
    hi = __float2half_rn(v);
    lo = __float2half_rn(v - __half2float(hi));
}

// ---------------------------------------------------------------------------
// Prep: split x,y fp32 -> fp16 hi/lo; transpose+split W. One launch.
// grid 256+18 CTAs.
// ---------------------------------------------------------------------------
__global__ void __launch_bounds__(256) prep_kernel(
        const float* __restrict__ x, const float* __restrict__ y,
        const float* __restrict__ Wq, const float* __restrict__ Wk,
        const float* __restrict__ Wv) {
    if (blockIdx.x < 256) {
        const int n4 = BB * TT * CC / 4;   // 131072
        for (int i = blockIdx.x * 256 + threadIdx.x; i < 2 * n4; i += 256 * 256) {
            bool isx = (i < n4);
            int j = isx ? i : i - n4;
            float4 v = reinterpret_cast<const float4*>(isx ? x : y)[j];
            __half h0, h1, h2, h3, l0, l1, l2, l3;
            split_h(v.x, h0, l0); split_h(v.y, h1, l1);
            split_h(v.z, h2, l2); split_h(v.w, h3, l3);
            uint2 hv = make_uint2(pack_h2(h0, h1), pack_h2(h2, h3));
            uint2 lv = make_uint2(pack_h2(l0, l1), pack_h2(l2, l3));
            *reinterpret_cast<uint2*>((isx ? g_xh : g_yh) + (size_t)j * 4) = hv;
            *reinterpret_cast<uint2*>((isx ? g_xl : g_yl) + (size_t)j * 4) = lv;
        }
    } else {
        const int sh = blockIdx.x - 256;      // 0..17
        const int sel = sh / HH, h = sh % HH;
        const float* W = (sel == 0 ? Wq : (sel == 1 ? Wk : Wv)) + (size_t)h * CC * DD;
        __half* oh = g_wTh + (size_t)sh * CC * DD;
        __half* ol = g_wTl + (size_t)sh * CC * DD;
        for (int i = threadIdx.x; i < CC * DD; i += 256) {
            int d = i >> 6, c = i & 63;
            float v = W[c * DD + d];
            __half hh, ll;
            split_h(v, hh, ll);
            oh[i] = hh;
            ol[i] = ll;
        }
    }
}

// ---------------------------------------------------------------------------
// Kernel 1: QKV projection via mma.sync (fp16 hi/lo, 3 chains), cp.async in.
// grid (TT/128, BH, 3), block 128 (4 warps x 32 rows).
// ---------------------------------------------------------------------------
#define XS 72
#define QKV_SMEM ((2*128*XS + 2*64*XS) * 2)

__global__ void __launch_bounds__(128) qkv_kernel() {
    extern __shared__ __align__(16) __half qsm[];
    __half* xh  = qsm;
    __half* xl  = xh + 128 * XS;
    __half* wTh = xl + 128 * XS;
    __half* wTl = wTh + 64 * XS;

    const int sel = blockIdx.z;
    const int bh  = blockIdx.y;
    const int b   = bh / HH, h = bh % HH;
    const int t0  = blockIdx.x * 128;

    const __half* srcH = (sel == 0 ? g_xh : g_yh) + ((size_t)b * TT + t0) * CC;
    const __half* srcL = (sel == 0 ? g_xl : g_yl) + ((size_t)b * TT + t0) * CC;
    const __half* wH   = g_wTh + (size_t)(sel * HH + h) * CC * DD;
    const __half* wL   = g_wTl + (size_t)(sel * HH + h) * CC * DD;

    const int tid  = threadIdx.x;
    const int wid  = tid >> 5, lane = tid & 31;
    const int g    = lane >> 2, tg = lane & 3;
    const int wrow = wid * 32;
    const int lrow = lane & 7;
    const int l8   = (lane >> 3) & 1;
    const int l16  = lane >> 4;

    const uint32_t xh_b  = smem_u32(xh);
    const uint32_t xl_b  = smem_u32(xl);
    const uint32_t wTh_b = smem_u32(wTh);
    const uint32_t wTl_b = smem_u32(wTl);

#pragma unroll
    for (int u = tid; u < 1024; u += 128) {
        int r = u >> 3, ch = (u & 7) * 8;
        uint32_t off = (uint32_t)(r * XS + ch) * 2;
        CP_ASYNC16(xh_b + off, srcH + (size_t)r * CC + ch);
        CP_ASYNC16(xl_b + off, srcL + (size_t)r * CC + ch);
    }
#pragma unroll
    for (int u = tid; u < 512; u += 128) {
        int r = u >> 3, ch = (u & 7) * 8;
        uint32_t off = (uint32_t)(r * XS + ch) * 2;
        CP_ASYNC16(wTh_b + off, wH + (size_t)r * CC + ch);
        CP_ASYNC16(wTl_b + off, wL + (size_t)r * CC + ch);
    }
    CP_COMMIT();
    CP_WAIT0();
    __syncthreads();

    float acc[2][8][4] = {};

#pragma unroll
    for (int kw = 0; kw < 2; kw++) {
        const int ck = kw * 32;
        uint32_t ah[2][2][4], al[2][2][4];
#pragma unroll
        for (int m = 0; m < 2; m++)
#pragma unroll
            for (int kk = 0; kk < 2; kk++) {
                uint32_t off = (uint32_t)((wrow + m * 16 + lrow + l8 * 8) * XS
                                          + ck + kk * 16 + l16 * 8) * 2;
                LDMATRIX_X4(ah[m][kk][0], ah[m][kk][1], ah[m][kk][2], ah[m][kk][3],
                            xh_b + off);
                LDMATRIX_X4(al[m][kk][0], al[m][kk][1], al[m][kk][2], al[m][kk][3],
                            xl_b + off);
            }
#pragma unroll
        for (int j = 0; j < 8; j++) {
            uint32_t boff = (uint32_t)((j * 8 + lrow) * XS + ck + (lane >> 3) * 8) * 2;
            uint32_t bh0, bh1, bh2, bh3, bl0, bl1, bl2, bl3;
            LDMATRIX_X4(bh0, bh1, bh2, bh3, wTh_b + boff);
            LDMATRIX_X4(bl0, bl1, bl2, bl3, wTl_b + boff);
#pragma unroll
            for (int m = 0; m < 2; m++) {
                MMA_F16(acc[m][j][0], acc[m][j][1], acc[m][j][2], acc[m][j][3],
                        ah[m][0][0], ah[m][0][1], ah[m][0][2], ah[m][0][3], bh0, bh1);
                MMA_F16(acc[m][j][0], acc[m][j][1], acc[m][j][2], acc[m][j][3],
                        ah[m][1][0], ah[m][1][1], ah[m][1][2], ah[m][1][3], bh2, bh3);
                MMA_F16(acc[m][j][0], acc[m][j][1], acc[m][j][2], acc[m][j][3],
                        ah[m][0][0], ah[m][0][1], ah[m][0][2], ah[m][0][3], bl0, bl1);
                MMA_F16(acc[m][j][0], acc[m][j][1], acc[m][j][2], acc[m][j][3],
                        ah[m][1][0], ah[m][1][1], ah[m][1][2], ah[m][1][3], bl2, bl3);
                MMA_F16(acc[m][j][0], acc[m][j][1], acc[m][j][2], acc[m][j][3],
                        al[m][0][0], al[m][0][1], al[m][0][2], al[m][0][3], bh0, bh1);
                MMA_F16(acc[m][j][0], acc[m][j][1], acc[m][j][2], acc[m][j][3],
                        al[m][1][0], al[m][1][1], al[m][1][2], al[m][1][3], bh2, bh3);
            }
        }
    }

    if (sel == 0) {
#pragma unroll
        for (int m = 0; m < 2; m++)
#pragma unroll
            for (int j = 0; j < 8; j++) {
                int r0 = t0 + wrow + m * 16 + g;
                int col = j * 8 + tg * 2;
                *reinterpret_cast<uint32_t*>(g_qh + ((size_t)bh * TT + r0) * DD + col) =
                    pack_h2(__float2half_rn(acc[m][j][0] * 0.125f),
                            __float2half_rn(acc[m][j][1] * 0.125f));
                *reinterpret_cast<uint32_t*>(g_qh + ((size_t)bh * TT + r0 + 8) * DD + col) =
                    pack_h2(__float2half_rn(acc[m][j][2] * 0.125f),
                            __float2half_rn(acc[m][j][3] * 0.125f));
            }
    } else if (sel == 1) {
#pragma unroll
        for (int m = 0; m < 2; m++)
#pragma unroll
            for (int j = 0; j < 8; j++) {
                int r0 = t0 + wrow + m * 16 + g;
                int col = j * 8 + tg * 2;
                __half h0, h1, h2, h3, l0, l1, l2, l3;
                split_h(acc[m][j][0], h0, l0); split_h(acc[m][j][1], h1, l1);
                split_h(acc[m][j][2], h2, l2); split_h(acc[m][j][3], h3, l3);
                size_t ba = ((size_t)bh * TT + r0) * DD + col;
                size_t bb = ((size_t)bh * TT + r0 + 8) * DD + col;
                *reinterpret_cast<uint32_t*>(g_kh + ba) = pack_h2(h0, h1);
                *reinterpret_cast<uint32_t*>(g_kh + bb) = pack_h2(h2, h3);
                *reinterpret_cast<uint32_t*>(g_kl + ba) = pack_h2(l0, l1);
                *reinterpret_cast<uint32_t*>(g_kl + bb) = pack_h2(l2, l3);
            }
    } else {
        __syncthreads();
        __half* vsh = xh;
        __half* vsl = xl;
#pragma unroll
        for (int m = 0; m < 2; m++)
#pragma unroll
            for (int j = 0; j < 8; j++) {
                int tA  = wrow + m * 16 + g;
                int tBr = tA + 8;
                int d0  = j * 8 + tg * 2;
                __half hh, ll;
                split_h(acc[m][j][0], hh, ll);
                vsh[(d0)     * 136 + tA]  = hh; vsl[(d0)     * 136 + tA]  = ll;
                split_h(acc[m][j][1], hh, ll);
                vsh[(d0 + 1) * 136 + tA]  = hh; vsl[(d0 + 1) * 136 + tA]  = ll;
                split_h(acc[m][j][2], hh, ll);
                vsh[(d0)     * 136 + tBr] = hh; vsl[(d0)     * 136 + tBr] = ll;
                split_h(acc[m][j][3], hh, ll);
                vsh[(d0 + 1) * 136 + tBr] = hh; vsl[(d0 + 1) * 136 + tBr] = ll;
            }
        __syncthreads();
        for (int u = tid; u < 1024; u += 128) {
            int d = u >> 4, tc = (u & 15) * 8;
            uint4 hv = *reinterpret_cast<uint4*>(vsh + d * 136 + tc);
            uint4 lv = *reinterpret_cast<uint4*>(vsl + d * 136 + tc);
            size_t dst = ((size_t)bh * DD + d) * TT + t0 + tc;
            *reinterpret_cast<uint4*>(g_vth + dst) = hv;
            *reinterpret_cast<uint4*>(g_vtl + dst) = lv;
        }
    }
}

// ---------------------------------------------------------------------------
// Kernel 2: causal flash attention via mma.sync (fp16, 2 chains).
// 128 q-rows per CTA, 8 warps, key tiles of 64, cp.async double buffer.
// __launch_bounds__(256, 2): force <=128 regs so 2 CTAs/SM co-reside.
// ---------------------------------------------------------------------------
#define KSTRIDE 72                      // fp16 elems per smem row (144 B)
#define ARR_B   (64 * KSTRIDE * 2)      // 9216 B per array
#define STG_B   (4 * ARR_B)             // 36864 B per stage
#define ATTN_SMEM (2 * STG_B)           // 73728 B

__global__ void __launch_bounds__(256, 2) attn_mma_kernel() {
    extern __shared__ __align__(16) char smem[];
    const uint32_t sbase = smem_u32(smem);

    const int tid  = threadIdx.x;
    const int wid  = tid >> 5, lane = tid & 31;
    const int g    = lane >> 2, tg = lane & 3;
    const int bid  = blockIdx.x;
    const int qt   = (TT / 128 - 1) - bid / BH;    // heavy tiles first
    const int bh   = bid % BH;
    const int q0   = qt * 128;
    const int wrow = wid * 16;
    const int njt  = 2 * qt + 2;

    const __half* khB = g_kh + (size_t)bh * TT * DD;
    const __half* klB = g_kl + (size_t)bh * TT * DD;
    const __half* vhB = g_vth + (size_t)bh * DD * TT;
    const __half* vlB = g_vtl + (size_t)bh * DD * TT;

    auto stage = [&](int jt) {
        const int j0 = jt * 64;
        const uint32_t so = sbase + (uint32_t)(jt & 1) * STG_B;
#pragma unroll
        for (int u = tid; u < 512; u += 256) {
            int r = u >> 3, ch = (u & 7) * 8;
            uint32_t off = (uint32_t)(r * (KSTRIDE * 2) + ch * 2);
            CP_ASYNC16(so + off,              khB + (size_t)(j0 + r) * DD + ch);
            CP_ASYNC16(so + ARR_B + off,      klB + (size_t)(j0 + r) * DD + ch);
            CP_ASYNC16(so + 2 * ARR_B + off,  vhB + (size_t)r * TT + j0 + ch);
            CP_ASYNC16(so + 3 * ARR_B + off,  vlB + (size_t)r * TT + j0 + ch);
        }
        CP_COMMIT();
    };

    // --- Q fragments (hi only, pre-scaled, loaded once) ---
    uint32_t qh[4][4];
    {
        const __half* qb = g_qh + ((size_t)bh * TT + q0 + wrow) * DD;
#pragma unroll
        for (int t = 0; t < 4; t++) {
            int col0 = t * 16 + tg * 2;
            qh[t][0] = *reinterpret_cast<const uint32_t*>(qb + (size_t)g * DD + col0);
            qh[t][1] = *reinterpret_cast<const uint32_t*>(qb + (size_t)(g + 8) * DD + col0);
            qh[t][2] = *reinterpret_cast<const uint32_t*>(qb + (size_t)g * DD + col0 + 8);
            qh[t][3] = *reinterpret_cast<const uint32_t*>(qb + (size_t)(g + 8) * DD + col0 + 8);
        }
    }

    float o[8][4];
#pragma unroll
    for (int j = 0; j < 8; j++)
#pragma unroll
        for (int e = 0; e < 4; e++) o[j][e] = 0.0f;
    float m0 = NEG_BIG, m1 = NEG_BIG, l0 = 0.0f, l1 = 0.0f;
    const int row0 = q0 + wrow + g, row1 = row0 + 8;
    const int rowmax = q0 + wrow + 15;

    const int lrow = lane & 7;
    const int lmi  = lane >> 3;

    stage(0);

    for (int jt = 0; jt < njt; jt++) {
        const int j0 = jt * 64;
        CP_WAIT0();
        __syncthreads();
        if (jt + 1 < njt) stage(jt + 1);

        if (j0 <= rowmax) {
            const uint32_t so = sbase + (uint32_t)(jt & 1) * STG_B;
            const uint32_t skh_b = so;
            const uint32_t skl_b = so + ARR_B;
            const uint32_t svh_b = so + 2 * ARR_B;
            const uint32_t svl_b = so + 3 * ARR_B;

            float c[8][4];
#pragma unroll
            for (int j = 0; j < 8; j++)
#pragma unroll
                for (int e = 0; e < 4; e++) c[j][e] = 0.0f;

#pragma unroll
            for (int j = 0; j < 8; j++) {
                uint32_t roff = (uint32_t)((j * 8 + lrow) * KSTRIDE + lmi * 8) * 2;
#pragma unroll
                for (int tp = 0; tp < 2; tp++) {
                    uint32_t coff = roff + (uint32_t)(tp * 64);
                    uint32_t kh0, kh1, kh2, kh3, kl0, kl1, kl2, kl3;
                    LDMATRIX_X4(kh0, kh1, kh2, kh3, skh_b + coff);
                    LDMATRIX_X4(kl0, kl1, kl2, kl3, skl_b + coff);
                    int t0s = 2 * tp, t1s = 2 * tp + 1;
                    MMA_F16(c[j][0], c[j][1], c[j][2], c[j][3],
                            qh[t0s][0], qh[t0s][1], qh[t0s][2], qh[t0s][3], kh0, kh1);
                    MMA_F16(c[j][0], c[j][1], c[j][2], c[j][3],
                            qh[t1s][0], qh[t1s][1], qh[t1s][2], qh[t1s][3], kh2, kh3);
                    MMA_F16(c[j][0], c[j][1], c[j][2], c[j][3],
                            qh[t0s][0], qh[t0s][1], qh[t0s][2], qh[t0s][3], kl0, kl1);
                    MMA_F16(c[j][0], c[j][1], c[j][2], c[j][3],
                            qh[t1s][0], qh[t1s][1], qh[t1s][2], qh[t1s][3], kl2, kl3);
                }
            }

            const bool m0p = (j0 + 63 > row0);
            const bool m1p = (j0 + 63 > row1);
            float mx0 = NEG_BIG, mx1 = NEG_BIG;
#pragma unroll
            for (int j = 0; j < 8; j++) {
#pragma unroll
                for (int e = 0; e < 2; e++) {
                    int col = j0 + j * 8 + tg * 2 + e;
                    float v0 = c[j][e];
                    float v1 = c[j][2 + e];
                    if (m0p && col > row0) v0 = NEG_BIG;
                    if (m1p && col > row1) v1 = NEG_BIG;
                    c[j][e] = v0; c[j][2 + e] = v1;
                    mx0 = fmaxf(mx0, v0); mx1 = fmaxf(mx1, v1);
                }
            }
            mx0 = fmaxf(mx0, __shfl_xor_sync(0xffffffffu, mx0, 1));
            mx0 = fmaxf(mx0, __shfl_xor_sync(0xffffffffu, mx0, 2));
            mx1 = fmaxf(mx1, __shfl_xor_sync(0xffffffffu, mx1, 1));
            mx1 = fmaxf(mx1, __shfl_xor_sync(0xffffffffu, mx1, 2));

            float mn0 = fmaxf(m0, mx0), mn1 = fmaxf(m1, mx1);
            float corr0 = __expf(m0 - mn0), corr1 = __expf(m1 - mn1);
            m0 = mn0; m1 = mn1;

            float s0 = 0.0f, s1 = 0.0f;
#pragma unroll
            for (int j = 0; j < 8; j++) {
#pragma unroll
                for (int e = 0; e < 2; e++) {
                    float p0 = __expf(c[j][e] - mn0);
                    float p1 = __expf(c[j][2 + e] - mn1);
                    c[j][e] = p0; c[j][2 + e] = p1;
                    s0 += p0; s1 += p1;
                }
            }
            s0 += __shfl_xor_sync(0xffffffffu, s0, 1);
            s0 += __shfl_xor_sync(0xffffffffu, s0, 2);
            s1 += __shfl_xor_sync(0xffffffffu, s1, 1);
            s1 += __shfl_xor_sync(0xffffffffu, s1, 2);
            l0 = l0 * corr0 + s0;
            l1 = l1 * corr1 + s1;

#pragma unroll
            for (int j = 0; j < 8; j++) {
                o[j][0] *= corr0; o[j][1] *= corr0;
                o[j][2] *= corr1; o[j][3] *= corr1;
            }

            uint32_t ph[4][4];
#pragma unroll
            for (int t = 0; t < 4; t++) {
                ph[t][0] = pack_h2(__float2half_rn(c[2*t][0]),   __float2half_rn(c[2*t][1]));
                ph[t][1] = pack_h2(__float2half_rn(c[2*t][2]),   __float2half_rn(c[2*t][3]));
                ph[t][2] = pack_h2(__float2half_rn(c[2*t+1][0]), __float2half_rn(c[2*t+1][1]));
                ph[t][3] = pack_h2(__float2half_rn(c[2*t+1][2]), __float2half_rn(c[2*t+1][3]));
            }

#pragma unroll
            for (int j = 0; j < 8; j++) {
                uint32_t roff = (uint32_t)((j * 8 + lrow) * KSTRIDE + lmi * 8) * 2;
#pragma unroll
                for (int tp = 0; tp < 2; tp++) {
                    uint32_t coff = roff + (uint32_t)(tp * 64);
                    uint32_t vh0, vh1, vh2, vh3, vl0, vl1, vl2, vl3;
                    LDMATRIX_X4(vh0, vh1, vh2, vh3, svh_b + coff);
                    LDMATRIX_X4(vl0, vl1, vl2, vl3, svl_b + coff);
                    int t0s = 2 * tp, t1s = 2 * tp + 1;
                    MMA_F16(o[j][0], o[j][1], o[j][2], o[j][3],
                            ph[t0s][0], ph[t0s][1], ph[t0s][2], ph[t0s][3], vh0, vh1);
                    MMA_F16(o[j][0], o[j][1], o[j][2], o[j][3],
                            ph[t1s][0], ph[t1s][1], ph[t1s][2], ph[t1s][3], vh2, vh3);
                    MMA_F16(o[j][0], o[j][1], o[j][2], o[j][3],
                            ph[t0s][0], ph[t0s][1], ph[t0s][2], ph[t0s][3], vl0, vl1);
                    MMA_F16(o[j][0], o[j][1], o[j][2], o[j][3],
                            ph[t1s][0], ph[t1s][1], ph[t1s][2], ph[t1s][3], vl2, vl3);
                }
            }
        }
    }

    {
        float inv0 = 1.0f / l0, inv1 = 1.0f / l1;
        float* op = g_o + ((size_t)bh * TT + q0 + wrow) * DD;
#pragma unroll
        for (int j = 0; j < 8; j++) {
            int col = j * 8 + tg * 2;
            *reinterpret_cast<float2*>(op + (size_t)g * DD + col) =
                make_float2(o[j][0] * inv0, o[j][1] * inv0);
            *reinterpret_cast<float2*>(op + (size_t)(g + 8) * DD + col) =
                make_float2(o[j][2] * inv1, o[j][3] * inv1);
        }
    }
}

// ---------------------------------------------------------------------------
// Kernel 3: output projection. grid (TT/64, BB) = 128 CTAs, 256 threads.
// ---------------------------------------------------------------------------
__global__ void __launch_bounds__(256) proj_kernel(
        const float* __restrict__ W_proj, const float* __restrict__ b_proj,
        float* __restrict__ out) {
    __shared__ __align__(16) float a_s[64][65];
    __shared__ __align__(16) float w_s[64][64];

    const int b  = blockIdx.y;
    const int t0 = blockIdx.x * 64;
    const int tid  = threadIdx.x;
    const int colg = tid & 7;
    const int rowg = tid >> 3;
    const int c0   = colg * 8;

    float acc[2][8] = {};
    for (int h = 0; h < HH; h++) {
        __syncthreads();
        const float* aptr = g_o + (((size_t)b * HH + h) * TT + t0) * DD;
        const float* wptr = W_proj + (size_t)h * DD * CC;
        for (int i = tid; i < 1024; i += 256) {
            int r = i >> 4, c4 = (i & 15) << 2;
            float4 v = reinterpret_cast<const float4*>(aptr)[i];
            float* dst = &a_s[r][c4];
            dst[0] = v.x; dst[1] = v.y; dst[2] = v.z; dst[3] = v.w;
            *reinterpret_cast<float4*>(&w_s[r][c4]) = reinterpret_cast<const float4*>(wptr)[i];
        }
        __syncthreads();
#pragma unroll 4
        for (int d = 0; d < DD; d++) {
            float4 w0 = *reinterpret_cast<const float4*>(&w_s[d][c0]);
            float4 w1 = *reinterpret_cast<const float4*>(&w_s[d][c0 + 4]);
#pragma unroll
            for (int i = 0; i < 2; i++) {
                float av = a_s[rowg + 32 * i][d];
                acc[i][0] = fmaf(av, w0.x, acc[i][0]);
                acc[i][1] = fmaf(av, w0.y, acc[i][1]);
                acc[i][2] = fmaf(av, w0.z, acc[i][2]);
                acc[i][3] = fmaf(av, w0.w, acc[i][3]);
                acc[i][4] = fmaf(av, w1.x, acc[i][4]);
                acc[i][5] = fmaf(av, w1.y, acc[i][5]);
                acc[i][6] = fmaf(av, w1.z, acc[i][6]);
                acc[i][7] = fmaf(av, w1.w, acc[i][7]);
            }
        }
    }

    float bp[8];
#pragma unroll
    for (int j = 0; j < 8; j++) bp[j] = b_proj[c0 + j];

    float* optr = out + ((size_t)b * TT + t0) * CC;
#pragma unroll
    for (int i = 0; i < 2; i++) {
        float4 o0 = make_float4(acc[i][0] + bp[0], acc[i][1] + bp[1],
                                acc[i][2] + bp[2], acc[i][3] + bp[3]);
        float4 o1 = make_float4(acc[i][4] + bp[4], acc[i][5] + bp[5],
                                acc[i][6] + bp[6], acc[i][7] + bp[7]);
        float* dst = optr + (size_t)(rowg + 32 * i) * CC + c0;
        *reinterpret_cast<float4*>(dst)     = o0;
        *reinterpret_cast<float4*>(dst + 4) = o1;
    }
}

// ---------------------------------------------------------------------------
extern "C" void kernel_launch(void* const* d_in, const int* in_sizes, int n_in,
                              void* d_out, int out_size) {
    const float* x      = (const float*)d_in[0];
    const float* y      = (const float*)d_in[1];
    const float* Wq     = (const float*)d_in[2];
    const float* Wk     = (const float*)d_in[3];
    const float* Wv     = (const float*)d_in[4];
    const float* W_proj = (const float*)d_in[5];
    const float* b_proj = (const float*)d_in[6];
    float* out = (float*)d_out;
    (void)in_sizes; (void)n_in; (void)out_size;

    static int inited = 0;
    if (!inited) {
        cudaFuncSetAttribute(qkv_kernel,
                             cudaFuncAttributeMaxDynamicSharedMemorySize, QKV_SMEM);
        cudaFuncSetAttribute(attn_mma_kernel,
                             cudaFuncAttributeMaxDynamicSharedMemorySize, ATTN_SMEM);
        cudaFuncSetAttribute(attn_mma_kernel,
                             cudaFuncAttributePreferredSharedMemoryCarveout,
                             cudaSharedmemCarveoutMaxShared);
        inited = 1;
    }

    prep_kernel<<<256 + 3 * HH, 256>>>(x, y, Wq, Wk, Wv);
    qkv_kernel<<<dim3(TT / 128, BH, 3), 128, QKV_SMEM>>>();
    attn_mma_kernel<<<(TT / 128) * BH, 256, ATTN_SMEM>>>();
    proj_kernel<<<dim3(TT / 64, BB), 256>>>(W_proj, b_proj, out);
}

// round 9
// speedup vs baseline: 1.1833x; 1.1833x over previous
#include <cuda_runtime.h>
#include <cuda_fp16.h>
#include <cstdint>

#define BB 4
#define TT 2048
#define CC 64
#define HH 6
#define DD 64
#define BH (BB*HH)
#define HD (HH*DD)
#define NEG_BIG (-1e30f)

// ---------------------------------------------------------------------------
// Scratch (__device__ globals; allocation-free rule). fp16 hi/lo splits.
// ---------------------------------------------------------------------------
__device__ __half g_xh [(size_t)BB*TT*CC];
__device__ __half g_xl [(size_t)BB*TT*CC];
__device__ __half g_yh [(size_t)BB*TT*CC];
__device__ __half g_yl [(size_t)BB*TT*CC];
__device__ __half g_wTh[(size_t)3*HH*CC*DD];   // qkv W transposed hi/lo
__device__ __half g_wTl[(size_t)3*HH*CC*DD];
__device__ __half g_wph[(size_t)CC*HD];        // W_proj^T [c][k] hi/lo
__device__ __half g_wpl[(size_t)CC*HD];

__device__ __half g_qh [(size_t)BH*TT*DD];     // q (pre-scaled 0.125, hi only)
__device__ __half g_kh [(size_t)BH*TT*DD];
__device__ __half g_kl [(size_t)BH*TT*DD];
__device__ __half g_vth[(size_t)BH*DD*TT];     // v transposed: [bh][d][t]
__device__ __half g_vtl[(size_t)BH*DD*TT];
__device__ __half g_ohf[(size_t)BB*TT*HD];     // O fp16 hi, [b*T+t][h*64+d]

__device__ __forceinline__ uint32_t smem_u32(const void* p) {
    uint32_t a;
    asm("{ .reg .u64 t; cvta.to.shared.u64 t, %1; cvt.u32.u64 %0, t; }"
        : "=r"(a) : "l"(p));
    return a;
}

#define LDMATRIX_X4(r0, r1, r2, r3, addr) \
    asm volatile("ldmatrix.sync.aligned.m8n8.x4.shared.b16 {%0,%1,%2,%3}, [%4];" \
        : "=r"(r0), "=r"(r1), "=r"(r2), "=r"(r3) : "r"(addr))

#define MMA_F16(d0, d1, d2, d3, a0, a1, a2, a3, b0, b1) \
    asm volatile("mma.sync.aligned.m16n8k16.row.col.f32.f16.f16.f32 " \
        "{%0,%1,%2,%3}, {%4,%5,%6,%7}, {%8,%9}, {%0,%1,%2,%3};" \
        : "+f"(d0), "+f"(d1), "+f"(d2), "+f"(d3) \
        : "r"(a0), "r"(a1), "r"(a2), "r"(a3), "r"(b0), "r"(b1))

#define CP_ASYNC16(saddr, gaddr) \
    asm volatile("cp.async.cg.shared.global [%0], [%1], 16;" \
        :: "r"(saddr), "l"(gaddr) : "memory")
#define CP_COMMIT() asm volatile("cp.async.commit_group;" ::: "memory")
#define CP_WAIT0()  asm volatile("cp.async.wait_group 0;" ::: "memory")

__device__ __forceinline__ uint32_t pack_h2(__half a, __half b) {
    return (uint32_t)__half_as_ushort(a) | ((uint32_t)__half_as_ushort(b) << 16);
}
__device__ __forceinline__ void split_h(float v, __half& hi, __half& lo) {
    hi = __float2half_rn(v);
    lo = __float2half_rn(v - __half2float(hi));
}

// ---------------------------------------------------------------------------
// Prep: split x,y; transpose+split Wq/Wk/Wv; transpose+split W_proj.
// grid 256 + 18 + 6 CTAs.
// ---------------------------------------------------------------------------
__global__ void __launch_bounds__(256) prep_kernel(
        const float* __restrict__ x, const float* __restrict__ y,
        const float* __restrict__ Wq, const float* __restrict__ Wk,
        const float* __restrict__ Wv, const float* __restrict__ W_proj) {
    if (blockIdx.x < 256) {
        const int n4 = BB * TT * CC / 4;
        for (int i = blockIdx.x * 256 + threadIdx.x; i < 2 * n4; i += 256 * 256) {
            bool isx = (i < n4);
            int j = isx ? i : i - n4;
            float4 v = reinterpret_cast<const float4*>(isx ? x : y)[j];
            __half h0, h1, h2, h3, l0, l1, l2, l3;
            split_h(v.x, h0, l0); split_h(v.y, h1, l1);
            split_h(v.z, h2, l2); split_h(v.w, h3, l3);
            uint2 hv = make_uint2(pack_h2(h0, h1), pack_h2(h2, h3));
            uint2 lv = make_uint2(pack_h2(l0, l1), pack_h2(l2, l3));
            *reinterpret_cast<uint2*>((isx ? g_xh : g_yh) + (size_t)j * 4) = hv;
            *reinterpret_cast<uint2*>((isx ? g_xl : g_yl) + (size_t)j * 4) = lv;
        }
    } else if (blockIdx.x < 256 + 18) {
        const int sh = blockIdx.x - 256;
        const int sel = sh / HH, h = sh % HH;
        const float* W = (sel == 0 ? Wq : (sel == 1 ? Wk : Wv)) + (size_t)h * CC * DD;
        __half* oh = g_wTh + (size_t)sh * CC * DD;
        __half* ol = g_wTl + (size_t)sh * CC * DD;
        for (int i = threadIdx.x; i < CC * DD; i += 256) {
            int d = i >> 6, c = i & 63;
            __half hh, ll;
            split_h(W[c * DD + d], hh, ll);
            oh[i] = hh;
            ol[i] = ll;
        }
    } else {
        // W_proj^T: g_wph[c][k] = W_proj[k][c], k-chunk per block
        const int k0 = (blockIdx.x - 256 - 18) * 64;
        for (int i = threadIdx.x; i < 64 * 64; i += 256) {
            int c = i >> 6, k = k0 + (i & 63);
            __half hh, ll;
            split_h(W_proj[(size_t)k * CC + c], hh, ll);
            g_wph[(size_t)c * HD + k] = hh;
            g_wpl[(size_t)c * HD + k] = ll;
        }
    }
}

// ---------------------------------------------------------------------------
// Kernel 1: QKV projection via mma.sync (fp16 hi/lo, 3 chains), cp.async in.
// grid (TT/128, BH, 3), block 128.
// ---------------------------------------------------------------------------
#define XS 72
#define QKV_SMEM ((2*128*XS + 2*64*XS) * 2)

__global__ void __launch_bounds__(128) qkv_kernel() {
    extern __shared__ __align__(16) __half qsm[];
    __half* xh  = qsm;
    __half* xl  = xh + 128 * XS;
    __half* wTh = xl + 128 * XS;
    __half* wTl = wTh + 64 * XS;

    const int sel = blockIdx.z;
    const int bh  = blockIdx.y;
    const int b   = bh / HH, h = bh % HH;
    const int t0  = blockIdx.x * 128;

    const __half* srcH = (sel == 0 ? g_xh : g_yh) + ((size_t)b * TT + t0) * CC;
    const __half* srcL = (sel == 0 ? g_xl : g_yl) + ((size_t)b * TT + t0) * CC;
    const __half* wH   = g_wTh + (size_t)(sel * HH + h) * CC * DD;
    const __half* wL   = g_wTl + (size_t)(sel * HH + h) * CC * DD;

    const int tid  = threadIdx.x;
    const int wid  = tid >> 5, lane = tid & 31;
    const int g    = lane >> 2, tg = lane & 3;
    const int wrow = wid * 32;
    const int lrow = lane & 7;
    const int l8   = (lane >> 3) & 1;
    const int l16  = lane >> 4;

    const uint32_t xh_b  = smem_u32(xh);
    const uint32_t xl_b  = smem_u32(xl);
    const uint32_t wTh_b = smem_u32(wTh);
    const uint32_t wTl_b = smem_u32(wTl);

#pragma unroll
    for (int u = tid; u < 1024; u += 128) {
        int r = u >> 3, ch = (u & 7) * 8;
        uint32_t off = (uint32_t)(r * XS + ch) * 2;
        CP_ASYNC16(xh_b + off, srcH + (size_t)r * CC + ch);
        CP_ASYNC16(xl_b + off, srcL + (size_t)r * CC + ch);
    }
#pragma unroll
    for (int u = tid; u < 512; u += 128) {
        int r = u >> 3, ch = (u & 7) * 8;
        uint32_t off = (uint32_t)(r * XS + ch) * 2;
        CP_ASYNC16(wTh_b + off, wH + (size_t)r * CC + ch);
        CP_ASYNC16(wTl_b + off, wL + (size_t)r * CC + ch);
    }
    CP_COMMIT();
    CP_WAIT0();
    __syncthreads();

    float acc[2][8][4] = {};

#pragma unroll
    for (int kw = 0; kw < 2; kw++) {
        const int ck = kw * 32;
        uint32_t ah[2][2][4], al[2][2][4];
#pragma unroll
        for (int m = 0; m < 2; m++)
#pragma unroll
            for (int kk = 0; kk < 2; kk++) {
                uint32_t off = (uint32_t)((wrow + m * 16 + lrow + l8 * 8) * XS
                                          + ck + kk * 16 + l16 * 8) * 2;
                LDMATRIX_X4(ah[m][kk][0], ah[m][kk][1], ah[m][kk][2], ah[m][kk][3],
                            xh_b + off);
                LDMATRIX_X4(al[m][kk][0], al[m][kk][1], al[m][kk][2], al[m][kk][3],
                            xl_b + off);
            }
#pragma unroll
        for (int j = 0; j < 8; j++) {
            uint32_t boff = (uint32_t)((j * 8 + lrow) * XS + ck + (lane >> 3) * 8) * 2;
            uint32_t bh0, bh1, bh2, bh3, bl0, bl1, bl2, bl3;
            LDMATRIX_X4(bh0, bh1, bh2, bh3, wTh_b + boff);
            LDMATRIX_X4(bl0, bl1, bl2, bl3, wTl_b + boff);
#pragma unroll
            for (int m = 0; m < 2; m++) {
                MMA_F16(acc[m][j][0], acc[m][j][1], acc[m][j][2], acc[m][j][3],
                        ah[m][0][0], ah[m][0][1], ah[m][0][2], ah[m][0][3], bh0, bh1);
                MMA_F16(acc[m][j][0], acc[m][j][1], acc[m][j][2], acc[m][j][3],
                        ah[m][1][0], ah[m][1][1], ah[m][1][2], ah[m][1][3], bh2, bh3);
                MMA_F16(acc[m][j][0], acc[m][j][1], acc[m][j][2], acc[m][j][3],
                        ah[m][0][0], ah[m][0][1], ah[m][0][2], ah[m][0][3], bl0, bl1);
                MMA_F16(acc[m][j][0], acc[m][j][1], acc[m][j][2], acc[m][j][3],
                        ah[m][1][0], ah[m][1][1], ah[m][1][2], ah[m][1][3], bl2, bl3);
                MMA_F16(acc[m][j][0], acc[m][j][1], acc[m][j][2], acc[m][j][3],
                        al[m][0][0], al[m][0][1], al[m][0][2], al[m][0][3], bh0, bh1);
                MMA_F16(acc[m][j][0], acc[m][j][1], acc[m][j][2], acc[m][j][3],
                        al[m][1][0], al[m][1][1], al[m][1][2], al[m][1][3], bh2, bh3);
            }
        }
    }

    if (sel == 0) {
#pragma unroll
        for (int m = 0; m < 2; m++)
#pragma unroll
            for (int j = 0; j < 8; j++) {
                int r0 = t0 + wrow + m * 16 + g;
                int col = j * 8 + tg * 2;
                *reinterpret_cast<uint32_t*>(g_qh + ((size_t)bh * TT + r0) * DD + col) =
                    pack_h2(__float2half_rn(acc[m][j][0] * 0.125f),
                            __float2half_rn(acc[m][j][1] * 0.125f));
                *reinterpret_cast<uint32_t*>(g_qh + ((size_t)bh * TT + r0 + 8) * DD + col) =
                    pack_h2(__float2half_rn(acc[m][j][2] * 0.125f),
                            __float2half_rn(acc[m][j][3] * 0.125f));
            }
    } else if (sel == 1) {
#pragma unroll
        for (int m = 0; m < 2; m++)
#pragma unroll
            for (int j = 0; j < 8; j++) {
                int r0 = t0 + wrow + m * 16 + g;
                int col = j * 8 + tg * 2;
                __half h0, h1, h2, h3, l0, l1, l2, l3;
                split_h(acc[m][j][0], h0, l0); split_h(acc[m][j][1], h1, l1);
                split_h(acc[m][j][2], h2, l2); split_h(acc[m][j][3], h3, l3);
                size_t ba = ((size_t)bh * TT + r0) * DD + col;
                size_t bb = ((size_t)bh * TT + r0 + 8) * DD + col;
                *reinterpret_cast<uint32_t*>(g_kh + ba) = pack_h2(h0, h1);
                *reinterpret_cast<uint32_t*>(g_kh + bb) = pack_h2(h2, h3);
                *reinterpret_cast<uint32_t*>(g_kl + ba) = pack_h2(l0, l1);
                *reinterpret_cast<uint32_t*>(g_kl + bb) = pack_h2(l2, l3);
            }
    } else {
        __syncthreads();
        __half* vsh = xh;
        __half* vsl = xl;
#pragma unroll
        for (int m = 0; m < 2; m++)
#pragma unroll
            for (int j = 0; j < 8; j++) {
                int tA  = wrow + m * 16 + g;
                int tBr = tA + 8;
                int d0  = j * 8 + tg * 2;
                __half hh, ll;
                split_h(acc[m][j][0], hh, ll);
                vsh[(d0)     * 136 + tA]  = hh; vsl[(d0)     * 136 + tA]  = ll;
                split_h(acc[m][j][1], hh, ll);
                vsh[(d0 + 1) * 136 + tA]  = hh; vsl[(d0 + 1) * 136 + tA]  = ll;
                split_h(acc[m][j][2], hh, ll);
                vsh[(d0)     * 136 + tBr] = hh; vsl[(d0)     * 136 + tBr] = ll;
                split_h(acc[m][j][3], hh, ll);
                vsh[(d0 + 1) * 136 + tBr] = hh; vsl[(d0 + 1) * 136 + tBr] = ll;
            }
        __syncthreads();
        for (int u = tid; u < 1024; u += 128) {
            int d = u >> 4, tc = (u & 15) * 8;
            uint4 hv = *reinterpret_cast<uint4*>(vsh + d * 136 + tc);
            uint4 lv = *reinterpret_cast<uint4*>(vsl + d * 136 + tc);
            size_t dst = ((size_t)bh * DD + d) * TT + t0 + tc;
            *reinterpret_cast<uint4*>(g_vth + dst) = hv;
            *reinterpret_cast<uint4*>(g_vtl + dst) = lv;
        }
    }
}

// ---------------------------------------------------------------------------
// Kernel 2: causal flash attention via mma.sync (fp16, 2 chains).
// Output: fp16 hi at [b*T+t][h*64+d] (proj A-operand layout).
// ---------------------------------------------------------------------------
#define KSTRIDE 72
#define ARR_B   (64 * KSTRIDE * 2)
#define STG_B   (4 * ARR_B)
#define ATTN_SMEM (2 * STG_B)

__global__ void __launch_bounds__(256, 2) attn_mma_kernel() {
    extern __shared__ __align__(16) char smem[];
    const uint32_t sbase = smem_u32(smem);

    const int tid  = threadIdx.x;
    const int wid  = tid >> 5, lane = tid & 31;
    const int g    = lane >> 2, tg = lane & 3;
    const int bid  = blockIdx.x;
    const int qt   = (TT / 128 - 1) - bid / BH;
    const int bh   = bid % BH;
    const int b    = bh / HH, h = bh % HH;
    const int q0   = qt * 128;
    const int wrow = wid * 16;
    const int njt  = 2 * qt + 2;

    const __half* khB = g_kh + (size_t)bh * TT * DD;
    const __half* klB = g_kl + (size_t)bh * TT * DD;
    const __half* vhB = g_vth + (size_t)bh * DD * TT;
    const __half* vlB = g_vtl + (size_t)bh * DD * TT;

    auto stage = [&](int jt) {
        const int j0 = jt * 64;
        const uint32_t so = sbase + (uint32_t)(jt & 1) * STG_B;
#pragma unroll
        for (int u = tid; u < 512; u += 256) {
            int r = u >> 3, ch = (u & 7) * 8;
            uint32_t off = (uint32_t)(r * (KSTRIDE * 2) + ch * 2);
            CP_ASYNC16(so + off,              khB + (size_t)(j0 + r) * DD + ch);
            CP_ASYNC16(so + ARR_B + off,      klB + (size_t)(j0 + r) * DD + ch);
            CP_ASYNC16(so + 2 * ARR_B + off,  vhB + (size_t)r * TT + j0 + ch);
            CP_ASYNC16(so + 3 * ARR_B + off,  vlB + (size_t)r * TT + j0 + ch);
        }
        CP_COMMIT();
    };

    uint32_t qh[4][4];
    {
        const __half* qb = g_qh + ((size_t)bh * TT + q0 + wrow) * DD;
#pragma unroll
        for (int t = 0; t < 4; t++) {
            int col0 = t * 16 + tg * 2;
            qh[t][0] = *reinterpret_cast<const uint32_t*>(qb + (size_t)g * DD + col0);
            qh[t][1] = *reinterpret_cast<const uint32_t*>(qb + (size_t)(g + 8) * DD + col0);
            qh[t][2] = *reinterpret_cast<const uint32_t*>(qb + (size_t)g * DD + col0 + 8);
            qh[t][3] = *reinterpret_cast<const uint32_t*>(qb + (size_t)(g + 8) * DD + col0 + 8);
        }
    }

    float o[8][4];
#pragma unroll
    for (int j = 0; j < 8; j++)
#pragma unroll
        for (int e = 0; e < 4; e++) o[j][e] = 0.0f;
    float m0 = NEG_BIG, m1 = NEG_BIG, l0 = 0.0f, l1 = 0.0f;
    const int row0 = q0 + wrow + g, row1 = row0 + 8;
    const int rowmax = q0 + wrow + 15;

    const int lrow = lane & 7;
    const int lmi  = lane >> 3;

    stage(0);

    for (int jt = 0; jt < njt; jt++) {
        const int j0 = jt * 64;
        CP_WAIT0();
        __syncthreads();
        if (jt + 1 < njt) stage(jt + 1);

        if (j0 <= rowmax) {
            const uint32_t so = sbase + (uint32_t)(jt & 1) * STG_B;
            const uint32_t skh_b = so;
            const uint32_t skl_b = so + ARR_B;
            const uint32_t svh_b = so + 2 * ARR_B;
            const uint32_t svl_b = so + 3 * ARR_B;

            float c[8][4];
#pragma unroll
            for (int j = 0; j < 8; j++)
#pragma unroll
                for (int e = 0; e < 4; e++) c[j][e] = 0.0f;

#pragma unroll
            for (int j = 0; j < 8; j++) {
                uint32_t roff = (uint32_t)((j * 8 + lrow) * KSTRIDE + lmi * 8) * 2;
#pragma unroll
                for (int tp = 0; tp < 2; tp++) {
                    uint32_t coff = roff + (uint32_t)(tp * 64);
                    uint32_t kh0, kh1, kh2, kh3, kl0, kl1, kl2, kl3;
                    LDMATRIX_X4(kh0, kh1, kh2, kh3, skh_b + coff);
                    LDMATRIX_X4(kl0, kl1, kl2, kl3, skl_b + coff);
                    int t0s = 2 * tp, t1s = 2 * tp + 1;
                    MMA_F16(c[j][0], c[j][1], c[j][2], c[j][3],
                            qh[t0s][0], qh[t0s][1], qh[t0s][2], qh[t0s][3], kh0, kh1);
                    MMA_F16(c[j][0], c[j][1], c[j][2], c[j][3],
                            qh[t1s][0], qh[t1s][1], qh[t1s][2], qh[t1s][3], kh2, kh3);
                    MMA_F16(c[j][0], c[j][1], c[j][2], c[j][3],
                            qh[t0s][0], qh[t0s][1], qh[t0s][2], qh[t0s][3], kl0, kl1);
                    MMA_F16(c[j][0], c[j][1], c[j][2], c[j][3],
                            qh[t1s][0], qh[t1s][1], qh[t1s][2], qh[t1s][3], kl2, kl3);
                }
            }

            const bool m0p = (j0 + 63 > row0);
            const bool m1p = (j0 + 63 > row1);
            float mx0 = NEG_BIG, mx1 = NEG_BIG;
#pragma unroll
            for (int j = 0; j < 8; j++) {
#pragma unroll
                for (int e = 0; e < 2; e++) {
                    int col = j0 + j * 8 + tg * 2 + e;
                    float v0 = c[j][e];
                    float v1 = c[j][2 + e];
                    if (m0p && col > row0) v0 = NEG_BIG;
                    if (m1p && col > row1) v1 = NEG_BIG;
                    c[j][e] = v0; c[j][2 + e] = v1;
                    mx0 = fmaxf(mx0, v0); mx1 = fmaxf(mx1, v1);
                }
            }
            mx0 = fmaxf(mx0, __shfl_xor_sync(0xffffffffu, mx0, 1));
            mx0 = fmaxf(mx0, __shfl_xor_sync(0xffffffffu, mx0, 2));
            mx1 = fmaxf(mx1, __shfl_xor_sync(0xffffffffu, mx1, 1));
            mx1 = fmaxf(mx1, __shfl_xor_sync(0xffffffffu, mx1, 2));

            float mn0 = fmaxf(m0, mx0), mn1 = fmaxf(m1, mx1);
            float corr0 = __expf(m0 - mn0), corr1 = __expf(m1 - mn1);
            m0 = mn0; m1 = mn1;

            float s0 = 0.0f, s1 = 0.0f;
#pragma unroll
            for (int j = 0; j < 8; j++) {
#pragma unroll
                for (int e = 0; e < 2; e++) {
                    float p0 = __expf(c[j][e] - mn0);
                    float p1 = __expf(c[j][2 + e] - mn1);
                    c[j][e] = p0; c[j][2 + e] = p1;
                    s0 += p0; s1 += p1;
                }
            }
            s0 += __shfl_xor_sync(0xffffffffu, s0, 1);
            s0 += __shfl_xor_sync(0xffffffffu, s0, 2);
            s1 += __shfl_xor_sync(0xffffffffu, s1, 1);
            s1 += __shfl_xor_sync(0xffffffffu, s1, 2);
            l0 = l0 * corr0 + s0;
            l1 = l1 * corr1 + s1;

#pragma unroll
            for (int j = 0; j < 8; j++) {
                o[j][0] *= corr0; o[j][1] *= corr0;
                o[j][2] *= corr1; o[j][3] *= corr1;
            }

            uint32_t ph[4][4];
#pragma unroll
            for (int t = 0; t < 4; t++) {
                ph[t][0] = pack_h2(__float2half_rn(c[2*t][0]),   __float2half_rn(c[2*t][1]));
                ph[t][1] = pack_h2(__float2half_rn(c[2*t][2]),   __float2half_rn(c[2*t][3]));
                ph[t][2] = pack_h2(__float2half_rn(c[2*t+1][0]), __float2half_rn(c[2*t+1][1]));
                ph[t][3] = pack_h2(__float2half_rn(c[2*t+1][2]), __float2half_rn(c[2*t+1][3]));
            }

#pragma unroll
            for (int j = 0; j < 8; j++) {
                uint32_t roff = (uint32_t)((j * 8 + lrow) * KSTRIDE + lmi * 8) * 2;
#pragma unroll
                for (int tp = 0; tp < 2; tp++) {
                    uint32_t coff = roff + (uint32_t)(tp * 64);
                    uint32_t vh0, vh1, vh2, vh3, vl0, vl1, vl2, vl3;
                    LDMATRIX_X4(vh0, vh1, vh2, vh3, svh_b + coff);
                    LDMATRIX_X4(vl0, vl1, vl2, vl3, svl_b + coff);
                    int t0s = 2 * tp, t1s = 2 * tp + 1;
                    MMA_F16(o[j][0], o[j][1], o[j][2], o[j][3],
                            ph[t0s][0], ph[t0s][1], ph[t0s][2], ph[t0s][3], vh0, vh1);
                    MMA_F16(o[j][0], o[j][1], o[j][2], o[j][3],
                            ph[t1s][0], ph[t1s][1], ph[t1s][2], ph[t1s][3], vh2, vh3);
                    MMA_F16(o[j][0], o[j][1], o[j][2], o[j][3],
                            ph[t0s][0], ph[t0s][1], ph[t0s][2], ph[t0s][3], vl0, vl1);
                    MMA_F16(o[j][0], o[j][1], o[j][2], o[j][3],
                            ph[t1s][0], ph[t1s][1], ph[t1s][2], ph[t1s][3], vl2, vl3);
                }
            }
        }
    }

    // normalize + store fp16 hi at [b*T+t][h*64+d]
    {
        float inv0 = 1.0f / l0, inv1 = 1.0f / l1;
        __half* opA = g_ohf + ((size_t)(b * TT + q0 + wrow + g)) * HD + h * DD;
        __half* opB = g_ohf + ((size_t)(b * TT + q0 + wrow + g + 8)) * HD + h * DD;
#pragma unroll
        for (int j = 0; j < 8; j++) {
            int col = j * 8 + tg * 2;
            *reinterpret_cast<uint32_t*>(opA + col) =
                pack_h2(__float2half_rn(o[j][0] * inv0), __float2half_rn(o[j][1] * inv0));
            *reinterpret_cast<uint32_t*>(opB + col) =
                pack_h2(__float2half_rn(o[j][2] * inv1), __float2half_rn(o[j][3] * inv1));
        }
    }
}

// ---------------------------------------------------------------------------
// Kernel 3: output projection via mma.sync (A hi x W hi/lo, 2 chains).
// [8192 x 384] x [384 x 64]. grid 128 CTAs, 128 threads (4 warps x 16 rows).
// k-chunks of 64, cp.async double buffer.
// ---------------------------------------------------------------------------
#define PST 72
#define PARR (64 * PST * 2)           // 9216 B
#define PSTG (3 * PARR)               // A_h, W_h, W_l = 27648 B
#define PROJ_SMEM (2 * PSTG)          // 55296 B

__global__ void __launch_bounds__(128) proj_mma_kernel(
        const float* __restrict__ b_proj, float* __restrict__ out) {
    extern __shared__ __align__(16) char psm[];
    const uint32_t sbase = smem_u32(psm);

    const int tid  = threadIdx.x;
    const int wid  = tid >> 5, lane = tid & 31;
    const int g    = lane >> 2, tg = lane & 3;
    const int lrow = lane & 7;
    const int l8   = (lane >> 3) & 1;
    const int l16  = lane >> 4;
    const int lmi  = lane >> 3;
    const int row0 = blockIdx.x * 64;
    const int wrow = wid * 16;

    const __half* aB = g_ohf + (size_t)row0 * HD;

    auto stage = [&](int kc) {
        const int k0 = kc * 64;
        const uint32_t so = sbase + (uint32_t)(kc & 1) * PSTG;
#pragma unroll
        for (int u = tid; u < 512; u += 128) {
            int r = u >> 3, ch = (u & 7) * 8;
            uint32_t off = (uint32_t)(r * PST + ch) * 2;
            CP_ASYNC16(so + off,            aB + (size_t)r * HD + k0 + ch);
            CP_ASYNC16(so + PARR + off,     g_wph + (size_t)r * HD + k0 + ch);
            CP_ASYNC16(so + 2 * PARR + off, g_wpl + (size_t)r * HD + k0 + ch);
        }
        CP_COMMIT();
    };

    float acc[8][4] = {};

    stage(0);
    for (int kc = 0; kc < 6; kc++) {
        CP_WAIT0();
        __syncthreads();
        if (kc + 1 < 6) stage(kc + 1);

        const uint32_t so = sbase + (uint32_t)(kc & 1) * PSTG;
        const uint32_t sa = so;
        const uint32_t swh = so + PARR;
        const uint32_t swl = so + 2 * PARR;

        // A fragments (hi only): 4 k16 groups
        uint32_t a[4][4];
#pragma unroll
        for (int kk = 0; kk < 4; kk++) {
            uint32_t off = (uint32_t)((wrow + lrow + l8 * 8) * PST
                                      + kk * 16 + l16 * 8) * 2;
            LDMATRIX_X4(a[kk][0], a[kk][1], a[kk][2], a[kk][3], sa + off);
        }
#pragma unroll
        for (int j = 0; j < 8; j++) {
            uint32_t roff = (uint32_t)((j * 8 + lrow) * PST + lmi * 8) * 2;
#pragma unroll
            for (int tp = 0; tp < 2; tp++) {
                uint32_t coff = roff + (uint32_t)(tp * 64);
                uint32_t wh0, wh1, wh2, wh3, wl0, wl1, wl2, wl3;
                LDMATRIX_X4(wh0, wh1, wh2, wh3, swh + coff);
                LDMATRIX_X4(wl0, wl1, wl2, wl3, swl + coff);
                int t0s = 2 * tp, t1s = 2 * tp + 1;
                MMA_F16(acc[j][0], acc[j][1], acc[j][2], acc[j][3],
                        a[t0s][0], a[t0s][1], a[t0s][2], a[t0s][3], wh0, wh1);
                MMA_F16(acc[j][0], acc[j][1], acc[j][2], acc[j][3],
                        a[t1s][0], a[t1s][1], a[t1s][2], a[t1s][3], wh2, wh3);
                MMA_F16(acc[j][0], acc[j][1], acc[j][2], acc[j][3],
                        a[t0s][0], a[t0s][1], a[t0s][2], a[t0s][3], wl0, wl1);
                MMA_F16(acc[j][0], acc[j][1], acc[j][2], acc[j][3],
                        a[t1s][0], a[t1s][1], a[t1s][2], a[t1s][3], wl2, wl3);
            }
        }
    }

    // epilogue: + b_proj, store fp32
    float* opA = out + (size_t)(row0 + wrow + g) * CC;
    float* opB = out + (size_t)(row0 + wrow + g + 8) * CC;
#pragma unroll
    for (int j = 0; j < 8; j++) {
        int col = j * 8 + tg * 2;
        float bp0 = b_proj[col], bp1 = b_proj[col + 1];
        *reinterpret_cast<float2*>(opA + col) =
            make_float2(acc[j][0] + bp0, acc[j][1] + bp1);
        *reinterpret_cast<float2*>(opB + col) =
            make_float2(acc[j][2] + bp0, acc[j][3] + bp1);
    }
}

// ---------------------------------------------------------------------------
extern "C" void kernel_launch(void* const* d_in, const int* in_sizes, int n_in,
                              void* d_out, int out_size) {
    const float* x      = (const float*)d_in[0];
    const float* y      = (const float*)d_in[1];
    const float* Wq     = (const float*)d_in[2];
    const float* Wk     = (const float*)d_in[3];
    const float* Wv     = (const float*)d_in[4];
    const float* W_proj = (const float*)d_in[5];
    const float* b_proj = (const float*)d_in[6];
    float* out = (float*)d_out;
    (void)in_sizes; (void)n_in; (void)out_size;

    static int inited = 0;
    if (!inited) {
        cudaFuncSetAttribute(qkv_kernel,
                             cudaFuncAttributeMaxDynamicSharedMemorySize, QKV_SMEM);
        cudaFuncSetAttribute(attn_mma_kernel,
                             cudaFuncAttributeMaxDynamicSharedMemorySize, ATTN_SMEM);
        cudaFuncSetAttribute(attn_mma_kernel,
                             cudaFuncAttributePreferredSharedMemoryCarveout,
                             cudaSharedmemCarveoutMaxShared);
        cudaFuncSetAttribute(proj_mma_kernel,
                             cudaFuncAttributeMaxDynamicSharedMemorySize, PROJ_SMEM);
        inited = 1;
    }

    prep_kernel<<<256 + 18 + 6, 256>>>(x, y, Wq, Wk, Wv, W_proj);
    qkv_kernel<<<dim3(TT / 128, BH, 3), 128, QKV_SMEM>>>();
    attn_mma_kernel<<<(TT / 128) * BH, 256, ATTN_SMEM>>>();
    proj_mma_kernel<<<(BB * TT) / 64, 128, PROJ_SMEM>>>(b_proj, out);
}